// round 9
// baseline (speedup 1.0000x reference)
#include <cuda_runtime.h>
#include <cuda_fp16.h>
#include <cstdint>

#define BSZ 256
#define MAX_LEN 1024
#define D 256
#define D_ATTN 128
#define NCTA 148
#define TOTAL_CHUNKS 32768   // (BSZ * MAX_LEN) / 8

// device scratch / sync state
__device__ float g_buf[BSZ * D];
__device__ int g_flag;
__device__ int k1_done;
__device__ int work_ctr;
__device__ int pref_ctr;

// ---------------------------------------------------------------------------
__device__ __forceinline__ uint32_t smem_u32(const void* p) {
    uint32_t a;
    asm("{ .reg .u64 t; cvta.to.shared.u64 t, %1; cvt.u32.u64 %0, t; }"
        : "=r"(a) : "l"(p));
    return a;
}
__device__ __forceinline__ float tanh_ap(float x) {
    float r;
    asm("tanh.approx.f32 %0, %1;" : "=f"(r) : "f"(x));
    return r;
}
__device__ __forceinline__ void mma_f16(float c[4], const uint32_t a[4],
                                        const uint32_t b[2]) {
    asm volatile(
        "mma.sync.aligned.m16n8k16.row.col.f32.f16.f16.f32 "
        "{%0,%1,%2,%3}, {%4,%5,%6,%7}, {%8,%9}, {%0,%1,%2,%3};\n"
        : "+f"(c[0]), "+f"(c[1]), "+f"(c[2]), "+f"(c[3])
        : "r"(a[0]), "r"(a[1]), "r"(a[2]), "r"(a[3]), "r"(b[0]), "r"(b[1]));
}
#define LDSM4(r0, r1, r2, r3, addr)                                           \
    asm volatile("ldmatrix.sync.aligned.m8n8.x4.shared.b16 {%0,%1,%2,%3}, [%4];" \
                 : "=r"(r0), "=r"(r1), "=r"(r2), "=r"(r3) : "r"(addr))
#define BAR2() asm volatile("bar.sync 2, 128;" ::: "memory")

__device__ __forceinline__ uint32_t pack_h2(float x, float y) {
    const __half2 h = __floats2half2_rn(x, y);
    return *(const uint32_t*)&h;
}
__device__ __forceinline__ uint4 pack8(const float4& a, const float4& b) {
    return make_uint4(pack_h2(a.x, a.y), pack_h2(a.z, a.w),
                      pack_h2(b.x, b.y), pack_h2(b.z, b.w));
}

// ---------------------------------------------------------------------------
__global__ void k0_init() {
    if (threadIdx.x == 0) {
        g_flag = 0; k1_done = 0; work_ctr = 0; pref_ctr = 0;
    }
}

// ---------------------------------------------------------------------------
// Streaming worker: prefetch emb_iseq into L2 while GEMM runs, then
// work-steal dot-product chunks (8 l-rows each). Chunk order: descending.
// ---------------------------------------------------------------------------
__device__ void stream_work(const float* __restrict__ emb_iseq,
                            float* __restrict__ out, const int lane)
{
    // ---- phase 1: prefetch (only while g not ready)
    for (;;) {
        if (*(volatile int*)&g_flag) break;
        int t;
        if (lane == 0) t = atomicAdd(&pref_ctr, 1);
        t = __shfl_sync(0xffffffffu, t, 0);
        if (t >= TOTAL_CHUNKS) break;
        const int idx = TOTAL_CHUNKS - 1 - t;
        const int b = idx >> 7;
        const int l = (idx & 127) * 8;
        const float4* base =
            (const float4*)(emb_iseq + ((size_t)b * MAX_LEN + l) * D);
        float d0 = 0.f, d1 = 0.f;
#pragma unroll
        for (int r = 0; r < 8; r++)
#pragma unroll
            for (int i = 0; i < 2; i++) {
                const float4 e = __ldcg(&base[r * 64 + i * 32 + lane]);
                d0 += e.x + e.y;
                d1 += e.z + e.w;
            }
        float dd = d0 + d1;
        asm volatile("" :: "f"(dd));   // keep the loads alive
    }

    // ---- phase 2: compute (same descending order -> L2 hits on prefetched)
    bool ready = false;
    int t;
    if (lane == 0) t = atomicAdd(&work_ctr, 1);
    t = __shfl_sync(0xffffffffu, t, 0);
    while (t < TOTAL_CHUNKS) {
        int tn;
        if (lane == 0) tn = atomicAdd(&work_ctr, 1);  // grab next early
        tn = __shfl_sync(0xffffffffu, tn, 0);

        const int idx = TOTAL_CHUNKS - 1 - t;
        const int b = idx >> 7;
        const int l = (idx & 127) * 8;
        const float4* base =
            (const float4*)(emb_iseq + ((size_t)b * MAX_LEN + l) * D);

        float4 e[8][2];
#pragma unroll
        for (int r = 0; r < 8; r++)
#pragma unroll
            for (int i = 0; i < 2; i++)
                e[r][i] = __ldcg(&base[r * 64 + i * 32 + lane]);

        if (!ready) {
            while (*(volatile int*)&g_flag == 0) __nanosleep(64);
            __threadfence();
            ready = true;
        }

        const float4* gp = (const float4*)(g_buf + (size_t)b * D);
        const float4 g0 = __ldcg(gp + lane);
        const float4 g1 = __ldcg(gp + lane + 32);

        float acc[8];
#pragma unroll
        for (int r = 0; r < 8; r++)
            acc[r] = e[r][0].x * g0.x + e[r][0].y * g0.y + e[r][0].z * g0.z +
                     e[r][0].w * g0.w + e[r][1].x * g1.x + e[r][1].y * g1.y +
                     e[r][1].z * g1.z + e[r][1].w * g1.w;
#pragma unroll
        for (int r = 0; r < 8; r++)
#pragma unroll
            for (int o = 16; o; o >>= 1)
                acc[r] += __shfl_xor_sync(0xffffffffu, acc[r], o);

        if (lane == 0) {
#pragma unroll
            for (int r = 0; r < 8; r++)
                out[(size_t)b * MAX_LEN + l + r] = acc[r];
        }
        t = tn;
    }
}

// ---------------------------------------------------------------------------
// Fused kernel: 148 CTAs x 512 threads (1/SM, all co-resident).
// Warps 0-3:  GEMM g[b][j] for j in {cta, cta+148}, then join streaming.
// Warps 4-15: streaming (prefetch, then dot products).
// smem: A = 4 k-tiles x 16KB @0 (w_f[j] fp16), B = 4 k-tiles x 32KB @65536
// (full emb_q fp16, loaded cooperatively by all 512 threads once).
// ---------------------------------------------------------------------------
#define B_OFF 65536
#define FUSED_SMEM (65536 + 131072 + 1024)

__global__ void __launch_bounds__(512, 1) fused(
    const float* __restrict__ emb_q,     // [BSZ, D]
    const float* __restrict__ emb_iseq,  // [BSZ, MAX_LEN, D]
    const float* __restrict__ w_f,       // [D, D_ATTN, D]
    const float* __restrict__ b_f,       // [D, D_ATTN]
    const float* __restrict__ w_h,       // [D_ATTN]
    float* __restrict__ out)             // [BSZ, MAX_LEN]
{
    extern __shared__ char dyn[];
    __shared__ float bias_s[D_ATTN], wh_s[D_ATTN];
    __shared__ float red[4][64];

    const int cta  = blockIdx.x;
    const int tid  = threadIdx.x;
    const int wid  = tid >> 5;
    const int lane = tid & 31;

    const uint32_t raw = smem_u32(dyn);
    const uint32_t dbase = (raw + 1023u) & ~1023u;
    char* dptr = dyn + (dbase - raw);

    // ---- cooperative B load: emb_q fp32 -> fp16 smem (all 512 threads)
    {
        const int r = tid >> 1;     // 0..255
        const int h = tid & 1;
#pragma unroll
        for (int kt = 0; kt < 4; kt++) {
            const float4* src =
                (const float4*)(emb_q + (size_t)r * 256 + kt * 64 + h * 32);
            float4 v[8];
#pragma unroll
            for (int q = 0; q < 8; q++) v[q] = src[q];
#pragma unroll
            for (int cc = 0; cc < 4; cc++) {
                const int cch = h * 4 + cc;
                *(uint4*)(dptr + B_OFF + kt * 32768 + r * 128 +
                          ((cch ^ (r & 7)) << 4)) = pack8(v[2 * cc], v[2 * cc + 1]);
            }
        }
        if (tid < D_ATTN) wh_s[tid] = w_h[tid];
    }
    __syncthreads();

    if (wid >= 4) {
        stream_work(emb_iseq, out, lane);
        return;
    }

    // =============== GEMM group: warps 0-3 (128 threads) ===============
    const int gid  = lane >> 2;
    const int tid4 = lane & 3;
    const int lrow = lane & 7;
    const int hlf  = (lane >> 3) & 1;
    const int hi   = lane >> 4;

    uint32_t roffA[2], swzA[2], roffB[4], swzB[4];
#pragma unroll
    for (int m = 0; m < 2; m++) {
        const int r = wid * 32 + m * 16 + hlf * 8 + lrow;
        roffA[m] = (uint32_t)r * 128;
        swzA[m]  = (uint32_t)(r & 7);
    }
#pragma unroll
    for (int pf = 0; pf < 4; pf++) {
        const int r = pf * 16 + hlf * 8 + lrow;
        roffB[pf] = (uint32_t)r * 128;
        swzB[pf]  = (uint32_t)(r & 7);
    }

    const int ntask = (cta < D - NCTA) ? 2 : 1;
    for (int task = 0; task < ntask; task++) {
        const int j = cta + task * NCTA;
        const float* Aj = w_f + (size_t)j * D_ATTN * D;

        // ---- A load: w_f[j] fp32 -> fp16 smem (1 row per thread per k-tile)
#pragma unroll
        for (int kt = 0; kt < 4; kt++) {
#pragma unroll
            for (int hh = 0; hh < 2; hh++) {
                const float4* src = (const float4*)(Aj + (size_t)tid * 256 +
                                                    kt * 64 + hh * 32);
                float4 v[8];
#pragma unroll
                for (int q = 0; q < 8; q++) v[q] = src[q];
#pragma unroll
                for (int cc = 0; cc < 4; cc++) {
                    const int cch = hh * 4 + cc;
                    *(uint4*)(dptr + kt * 16384 + tid * 128 +
                              ((cch ^ (tid & 7)) << 4)) =
                        pack8(v[2 * cc], v[2 * cc + 1]);
                }
            }
        }
        bias_s[tid] = b_f[j * D_ATTN + tid];
        BAR2();

        // ---- 4 n-passes of 64 b-columns
        for (int p = 0; p < 4; p++) {
            float acc[2][8][4];
#pragma unroll
            for (int m = 0; m < 2; m++)
#pragma unroll
                for (int n = 0; n < 8; n++)
#pragma unroll
                    for (int q = 0; q < 4; q++) acc[m][n][q] = 0.0f;

#pragma unroll
            for (int kt = 0; kt < 4; kt++) {
                const uint32_t aB = dbase + (uint32_t)kt * 16384;
                const uint32_t bB = dbase + B_OFF + (uint32_t)kt * 32768 +
                                    (uint32_t)p * 8192;
#pragma unroll
                for (int ks = 0; ks < 4; ks++) {
                    const uint32_t ch = (uint32_t)(ks * 2 + hi);
                    uint32_t af[2][4], bf[8][2];
#pragma unroll
                    for (int m = 0; m < 2; m++)
                        LDSM4(af[m][0], af[m][1], af[m][2], af[m][3],
                              aB + roffA[m] + ((ch ^ swzA[m]) << 4));
#pragma unroll
                    for (int pf = 0; pf < 4; pf++) {
                        uint32_t r0, r1, r2, r3;
                        LDSM4(r0, r1, r2, r3,
                              bB + roffB[pf] + ((ch ^ swzB[pf]) << 4));
                        bf[2 * pf][0] = r0; bf[2 * pf + 1][0] = r1;
                        bf[2 * pf][1] = r2; bf[2 * pf + 1][1] = r3;
                    }
#pragma unroll
                    for (int m = 0; m < 2; m++)
#pragma unroll
                        for (int n = 0; n < 8; n++)
                            mma_f16(acc[m][n], af[m], bf[n]);
                }
            }

            // epilogue: tanh + w_h partial over this warp's 32 a-rows
            float biasv[2][2], whv[2][2];
#pragma unroll
            for (int m = 0; m < 2; m++)
#pragma unroll
                for (int h = 0; h < 2; h++) {
                    const int a = wid * 32 + m * 16 + h * 8 + gid;
                    biasv[m][h] = bias_s[a];
                    whv[m][h]   = wh_s[a];
                }
#pragma unroll
            for (int n = 0; n < 8; n++) {
                float p0 = 0.0f, p1 = 0.0f;
#pragma unroll
                for (int m = 0; m < 2; m++) {
                    p0 += tanh_ap(acc[m][n][0] + biasv[m][0]) * whv[m][0]
                        + tanh_ap(acc[m][n][2] + biasv[m][1]) * whv[m][1];
                    p1 += tanh_ap(acc[m][n][1] + biasv[m][0]) * whv[m][0]
                        + tanh_ap(acc[m][n][3] + biasv[m][1]) * whv[m][1];
                }
#pragma unroll
                for (int o = 4; o <= 16; o <<= 1) {
                    p0 += __shfl_xor_sync(0xffffffffu, p0, o);
                    p1 += __shfl_xor_sync(0xffffffffu, p1, o);
                }
                if (gid == 0) {
                    const int col = n * 8 + tid4 * 2;
                    red[wid][col]     = p0;
                    red[wid][col + 1] = p1;
                }
            }
            BAR2();
            if (tid < 64)
                g_buf[(size_t)(p * 64 + tid) * D + j] =
                    red[0][tid] + red[1][tid] + red[2][tid] + red[3][tid];
            BAR2();
        }
    }

    __threadfence();
    BAR2();
    if (tid == 0) {
        const int old = atomicAdd(&k1_done, 1);
        if (old == NCTA - 1) atomicExch(&g_flag, 1);
    }

    // join the streaming pool
    stream_work(emb_iseq, out, lane);
}

// ---------------------------------------------------------------------------

extern "C" void kernel_launch(void* const* d_in, const int* in_sizes, int n_in,
                              void* d_out, int out_size)
{
    const float* emb_q    = (const float*)d_in[0];
    const float* emb_iseq = (const float*)d_in[1];
    const float* w_f      = (const float*)d_in[2];
    const float* b_f      = (const float*)d_in[3];
    const float* w_h      = (const float*)d_in[4];
    float* out = (float*)d_out;

    cudaFuncSetAttribute(fused, cudaFuncAttributeMaxDynamicSharedMemorySize,
                         FUSED_SMEM);

    k0_init<<<1, 32>>>();
    fused<<<NCTA, 512, FUSED_SMEM>>>(emb_q, emb_iseq, w_f, b_f, w_h, out);
}

// round 10
// speedup vs baseline: 1.2044x; 1.2044x over previous
#include <cuda_runtime.h>
#include <cuda_fp16.h>
#include <cstdint>

#define BSZ 256
#define MAX_LEN 1024
#define D 256
#define D_ATTN 128
#define NCTA 148
#define TOTAL_CHUNKS 32768        // (BSZ*MAX_LEN)/8 rows per chunk
#define NWARPS_ALL (NCTA * 16)

// device scratch / sync state (reset by the kernel itself at the end)
__device__ float g_buf[BSZ * D];
__device__ int g_flag   = 0;
__device__ int k1_done  = 0;
__device__ int work_ctr = 0;
__device__ int warp_done = 0;

// ---------------------------------------------------------------------------
__device__ __forceinline__ uint32_t smem_u32(const void* p) {
    uint32_t a;
    asm("{ .reg .u64 t; cvta.to.shared.u64 t, %1; cvt.u32.u64 %0, t; }"
        : "=r"(a) : "l"(p));
    return a;
}
__device__ __forceinline__ float tanh_ap(float x) {
    float r;
    asm("tanh.approx.f32 %0, %1;" : "=f"(r) : "f"(x));
    return r;
}
__device__ __forceinline__ void mma_f16(float c[4], const uint32_t a[4],
                                        const uint32_t b[2]) {
    asm volatile(
        "mma.sync.aligned.m16n8k16.row.col.f32.f16.f16.f32 "
        "{%0,%1,%2,%3}, {%4,%5,%6,%7}, {%8,%9}, {%0,%1,%2,%3};\n"
        : "+f"(c[0]), "+f"(c[1]), "+f"(c[2]), "+f"(c[3])
        : "r"(a[0]), "r"(a[1]), "r"(a[2]), "r"(a[3]), "r"(b[0]), "r"(b[1]));
}
#define LDSM4(r0, r1, r2, r3, addr)                                           \
    asm volatile("ldmatrix.sync.aligned.m8n8.x4.shared.b16 {%0,%1,%2,%3}, [%4];" \
                 : "=r"(r0), "=r"(r1), "=r"(r2), "=r"(r3) : "r"(addr))
#define BAR1() asm volatile("bar.sync 1, 256;" ::: "memory")

__device__ __forceinline__ uint32_t pack_h2(float x, float y) {
    const __half2 h = __floats2half2_rn(x, y);
    return *(const uint32_t*)&h;
}
__device__ __forceinline__ uint4 pack8(const float4& a, const float4& b) {
    return make_uint4(pack_h2(a.x, a.y), pack_h2(a.z, a.w),
                      pack_h2(b.x, b.y), pack_h2(b.z, b.w));
}

// ---------------------------------------------------------------------------
// Streaming worker: atomically grab 8-row chunks of emb_iseq, dot with g.
// Single read of every byte. Early-grab hides the atomic latency.
// ---------------------------------------------------------------------------
__device__ __forceinline__ void stream_work(
    const float* __restrict__ emb_iseq, float* __restrict__ out, const int lane)
{
    bool ready = false;
    int t;
    if (lane == 0) t = atomicAdd(&work_ctr, 1);
    t = __shfl_sync(0xffffffffu, t, 0);

    while (t < TOTAL_CHUNKS) {
        const int b = t >> 7;
        const int l = (t & 127) * 8;
        const float4* base =
            (const float4*)(emb_iseq + ((size_t)b * MAX_LEN + l) * D);

        float4 e[8][2];
#pragma unroll
        for (int r = 0; r < 8; r++)
#pragma unroll
            for (int i = 0; i < 2; i++)
                e[r][i] = __ldcs(&base[r * 64 + i * 32 + lane]);

        int tn;
        if (lane == 0) tn = atomicAdd(&work_ctr, 1);   // overlap with loads
        tn = __shfl_sync(0xffffffffu, tn, 0);

        if (!ready) {
            while (*(volatile int*)&g_flag == 0) __nanosleep(64);
            __threadfence();
            ready = true;
        }

        const float4* gp = (const float4*)(g_buf + (size_t)b * D);
        const float4 g0 = __ldcg(gp + lane);
        const float4 g1 = __ldcg(gp + lane + 32);

        float acc[8];
#pragma unroll
        for (int r = 0; r < 8; r++)
            acc[r] = e[r][0].x * g0.x + e[r][0].y * g0.y + e[r][0].z * g0.z +
                     e[r][0].w * g0.w + e[r][1].x * g1.x + e[r][1].y * g1.y +
                     e[r][1].z * g1.z + e[r][1].w * g1.w;
#pragma unroll
        for (int r = 0; r < 8; r++)
#pragma unroll
            for (int o = 16; o; o >>= 1)
                acc[r] += __shfl_xor_sync(0xffffffffu, acc[r], o);

        if (lane == 0) {
#pragma unroll
            for (int r = 0; r < 8; r++)
                out[(size_t)b * MAX_LEN + l + r] = acc[r];
        }
        t = tn;
    }

    // last warp overall resets sync state for the next graph replay
    __threadfence();
    if (lane == 0) {
        const int old = atomicAdd(&warp_done, 1);
        if (old == NWARPS_ALL - 1) {
            g_flag = 0; k1_done = 0; work_ctr = 0;
            __threadfence();
            warp_done = 0;
        }
    }
}

// ---------------------------------------------------------------------------
// Fused kernel: 148 CTAs x 512 threads (1/SM, co-resident).
// All 512: cooperative emb_q fp32->fp16 into smem (B operand).
// Warps 0-7:  GEMM g[b][j] for j in {cta, cta+148}, then JOIN streaming.
// Warps 8-15: streaming from t=0.
// smem: A = 4 k-tiles x 16KB @0 (w_f[j] fp16), B = 4 k-tiles x 32KB @65536.
// ---------------------------------------------------------------------------
#define B_OFF 65536
#define FUSED_SMEM (65536 + 131072 + 1024)

__global__ void __launch_bounds__(512, 1) fused(
    const float* __restrict__ emb_q,     // [BSZ, D]
    const float* __restrict__ emb_iseq,  // [BSZ, MAX_LEN, D]
    const float* __restrict__ w_f,       // [D, D_ATTN, D]
    const float* __restrict__ b_f,       // [D, D_ATTN]
    const float* __restrict__ w_h,       // [D_ATTN]
    float* __restrict__ out)             // [BSZ, MAX_LEN]
{
    extern __shared__ char dyn[];
    __shared__ float bias_s[D_ATTN], wh_s[D_ATTN];
    __shared__ float red[2][128];

    const int cta  = blockIdx.x;
    const int tid  = threadIdx.x;
    const int wid  = tid >> 5;
    const int lane = tid & 31;

    const uint32_t raw = smem_u32(dyn);
    const uint32_t dbase = (raw + 1023u) & ~1023u;
    char* dptr = dyn + (dbase - raw);

    // ---- cooperative B load: emb_q fp32 -> fp16 smem (all 512 threads)
    {
        const int r = tid >> 1;     // 0..255
        const int h = tid & 1;
#pragma unroll
        for (int kt = 0; kt < 4; kt++) {
            const float4* src =
                (const float4*)(emb_q + (size_t)r * 256 + kt * 64 + h * 32);
            float4 v[8];
#pragma unroll
            for (int q = 0; q < 8; q++) v[q] = src[q];
#pragma unroll
            for (int cc = 0; cc < 4; cc++) {
                const int cch = h * 4 + cc;
                *(uint4*)(dptr + B_OFF + kt * 32768 + r * 128 +
                          ((cch ^ (r & 7)) << 4)) = pack8(v[2 * cc], v[2 * cc + 1]);
            }
        }
        if (tid < D_ATTN) wh_s[tid] = w_h[tid];
    }
    __syncthreads();

    if (wid >= 8) {
        stream_work(emb_iseq, out, lane);
        return;
    }

    // =============== GEMM group: warps 0-7 (256 threads) ===============
    const int c  = tid & 7;
    const int rb = tid >> 3;
    const int wm = wid >> 2, wn = wid & 3;
    const int gid = lane >> 2, tid4 = lane & 3;
    const int lrow = lane & 7, half = (lane >> 3) & 1, hi = lane >> 4;

    uint32_t roffA[4], swzA[4], roffB[2], swzB[2];
#pragma unroll
    for (int m = 0; m < 4; m++) {
        const int r = wm * 64 + m * 16 + half * 8 + lrow;
        roffA[m] = (uint32_t)r * 128;
        swzA[m]  = (uint32_t)(r & 7);
    }
#pragma unroll
    for (int pf = 0; pf < 2; pf++) {
        const int r = wn * 32 + pf * 16 + half * 8 + lrow;
        roffB[pf] = (uint32_t)r * 128;
        swzB[pf]  = (uint32_t)(r & 7);
    }

    const int ntask = (cta < D - NCTA) ? 2 : 1;
    for (int task = 0; task < ntask; task++) {
        const int j = cta + task * NCTA;
        const float* Aj = w_f + (size_t)j * D_ATTN * D;

        // A: w_f[j] fp32 -> fp16 smem (4 rows/thread per k-tile pattern)
#pragma unroll
        for (int kt = 0; kt < 4; kt++) {
            float4 ra[4][2];
#pragma unroll
            for (int i = 0; i < 4; i++) {
                const int r = rb + 32 * i;  // 0..127
                const float* p = Aj + (size_t)r * 256 + kt * 64 + c * 8;
                ra[i][0] = *(const float4*)p;
                ra[i][1] = *(const float4*)(p + 4);
            }
#pragma unroll
            for (int i = 0; i < 4; i++) {
                const int r = rb + 32 * i;
                *(uint4*)(dptr + kt * 16384 + r * 128 + ((c ^ (r & 7)) << 4)) =
                    pack8(ra[i][0], ra[i][1]);
            }
        }
        if (tid < D_ATTN) bias_s[tid] = b_f[j * D_ATTN + tid];
        BAR1();

        // two n-passes of 128 b-columns each
#pragma unroll
        for (int p = 0; p < 2; p++) {
            float acc[4][4][4];
#pragma unroll
            for (int m = 0; m < 4; m++)
#pragma unroll
                for (int n = 0; n < 4; n++)
#pragma unroll
                    for (int q = 0; q < 4; q++) acc[m][n][q] = 0.0f;

#pragma unroll
            for (int kt = 0; kt < 4; kt++) {
                const uint32_t aB = dbase + (uint32_t)kt * 16384;
                const uint32_t bB = dbase + B_OFF + (uint32_t)kt * 32768 +
                                    (uint32_t)p * 16384;
#pragma unroll
                for (int ks = 0; ks < 4; ks++) {
                    const uint32_t ch = (uint32_t)(ks * 2 + hi);
                    uint32_t af[4][4], bf[4][2];
#pragma unroll
                    for (int m = 0; m < 4; m++)
                        LDSM4(af[m][0], af[m][1], af[m][2], af[m][3],
                              aB + roffA[m] + ((ch ^ swzA[m]) << 4));
#pragma unroll
                    for (int pf = 0; pf < 2; pf++) {
                        uint32_t r0, r1, r2, r3;
                        LDSM4(r0, r1, r2, r3,
                              bB + roffB[pf] + ((ch ^ swzB[pf]) << 4));
                        bf[2 * pf][0] = r0; bf[2 * pf + 1][0] = r1;
                        bf[2 * pf][1] = r2; bf[2 * pf + 1][1] = r3;
                    }
#pragma unroll
                    for (int m = 0; m < 4; m++)
#pragma unroll
                        for (int n = 0; n < 4; n++)
                            mma_f16(acc[m][n], af[m], bf[n]);
                }
            }

            // epilogue
            float biasv[4][2], whv[4][2];
#pragma unroll
            for (int m = 0; m < 4; m++)
#pragma unroll
                for (int h = 0; h < 2; h++) {
                    const int a = wm * 64 + m * 16 + h * 8 + gid;
                    biasv[m][h] = bias_s[a];
                    whv[m][h]   = wh_s[a];
                }
#pragma unroll
            for (int n = 0; n < 4; n++) {
                float p0 = 0.0f, p1 = 0.0f;
#pragma unroll
                for (int m = 0; m < 4; m++) {
                    p0 += tanh_ap(acc[m][n][0] + biasv[m][0]) * whv[m][0]
                        + tanh_ap(acc[m][n][2] + biasv[m][1]) * whv[m][1];
                    p1 += tanh_ap(acc[m][n][1] + biasv[m][0]) * whv[m][0]
                        + tanh_ap(acc[m][n][3] + biasv[m][1]) * whv[m][1];
                }
#pragma unroll
                for (int o = 4; o <= 16; o <<= 1) {
                    p0 += __shfl_xor_sync(0xffffffffu, p0, o);
                    p1 += __shfl_xor_sync(0xffffffffu, p1, o);
                }
                if (gid == 0) {
                    const int col = wn * 32 + n * 8 + tid4 * 2;
                    red[wm][col]     = p0;
                    red[wm][col + 1] = p1;
                }
            }
            BAR1();
            if (tid < 128)
                g_buf[(size_t)(p * 128 + tid) * D + j] =
                    red[0][tid] + red[1][tid];
            BAR1();
        }
    }

    __threadfence();
    if (tid == 0) {
        const int old = atomicAdd(&k1_done, 1);
        if (old == NCTA - 1) atomicExch(&g_flag, 1);
    }

    // join the streaming pool
    stream_work(emb_iseq, out, lane);
}

// ---------------------------------------------------------------------------

extern "C" void kernel_launch(void* const* d_in, const int* in_sizes, int n_in,
                              void* d_out, int out_size)
{
    const float* emb_q    = (const float*)d_in[0];
    const float* emb_iseq = (const float*)d_in[1];
    const float* w_f      = (const float*)d_in[2];
    const float* b_f      = (const float*)d_in[3];
    const float* w_h      = (const float*)d_in[4];
    float* out = (float*)d_out;

    cudaFuncSetAttribute(fused, cudaFuncAttributeMaxDynamicSharedMemorySize,
                         FUSED_SMEM);

    fused<<<NCTA, 512, FUSED_SMEM>>>(emb_q, emb_iseq, w_f, b_f, w_h, out);
}

// round 11
// speedup vs baseline: 1.2770x; 1.0603x over previous
#include <cuda_runtime.h>
#include <cuda_fp16.h>
#include <cstdint>

#define BSZ 256
#define MAX_LEN 1024
#define D 256
#define D_ATTN 128
#define NCTA 148

// prefetch coverage: first PREF_F4 float4s of emb_iseq (= 96 MB, b < 96)
#define PREF_F4 (96 * 1024 * 1024 / 16)

__device__ float g_buf[BSZ * D];   // g[b][j]

// ---------------------------------------------------------------------------
__device__ __forceinline__ uint32_t smem_u32(const void* p) {
    uint32_t a;
    asm("{ .reg .u64 t; cvta.to.shared.u64 t, %1; cvt.u32.u64 %0, t; }"
        : "=r"(a) : "l"(p));
    return a;
}
__device__ __forceinline__ float tanh_ap(float x) {
    float r;
    asm("tanh.approx.f32 %0, %1;" : "=f"(r) : "f"(x));
    return r;
}
__device__ __forceinline__ void mma_f16(float c[4], const uint32_t a[4],
                                        const uint32_t b[2]) {
    asm volatile(
        "mma.sync.aligned.m16n8k16.row.col.f32.f16.f16.f32 "
        "{%0,%1,%2,%3}, {%4,%5,%6,%7}, {%8,%9}, {%0,%1,%2,%3};\n"
        : "+f"(c[0]), "+f"(c[1]), "+f"(c[2]), "+f"(c[3])
        : "r"(a[0]), "r"(a[1]), "r"(a[2]), "r"(a[3]), "r"(b[0]), "r"(b[1]));
}
#define LDSM4(r0, r1, r2, r3, addr)                                           \
    asm volatile("ldmatrix.sync.aligned.m8n8.x4.shared.b16 {%0,%1,%2,%3}, [%4];" \
                 : "=r"(r0), "=r"(r1), "=r"(r2), "=r"(r3) : "r"(addr))
#define BAR1() asm volatile("bar.sync 1, 256;" ::: "memory")

__device__ __forceinline__ uint32_t pack_h2(float x, float y) {
    const __half2 h = __floats2half2_rn(x, y);
    return *(const uint32_t*)&h;
}
__device__ __forceinline__ uint4 pack8(const float4& a, const float4& b) {
    return make_uint4(pack_h2(a.x, a.y), pack_h2(a.z, a.w),
                      pack_h2(b.x, b.y), pack_h2(b.z, b.w));
}

// ---------------------------------------------------------------------------
// Kernel 1: 148 CTAs x 512 threads (1/SM).
// All 512: cooperative emb_q fp32->fp16 smem conversion (B operand, once).
// Warps 0-7:  GEMM g[b][j] for j in {cta, cta+148} (108x2 + 40x1 = 256 j).
// Warps 8-15: prefetch first 96MB of emb_iseq into L2 (k2 consumes it first).
// smem: A = 4 k-tiles x 16KB @0 (w_f[j] fp16), B = 4 k-tiles x 32KB @65536.
// ---------------------------------------------------------------------------
#define B_OFF 65536
#define K1_SMEM (65536 + 131072 + 1024)

__global__ void __launch_bounds__(512, 1) k1_mma(
    const float* __restrict__ emb_q,     // [BSZ, D]
    const float* __restrict__ emb_iseq,  // [BSZ, MAX_LEN, D]
    const float* __restrict__ w_f,       // [D, D_ATTN, D]
    const float* __restrict__ b_f,       // [D, D_ATTN]
    const float* __restrict__ w_h)       // [D_ATTN]
{
    extern __shared__ char dyn[];
    __shared__ float bias_s[D_ATTN], wh_s[D_ATTN];
    __shared__ float red[2][128];

    const int cta  = blockIdx.x;
    const int tid  = threadIdx.x;
    const int wid  = tid >> 5;
    const int lane = tid & 31;

    const uint32_t raw = smem_u32(dyn);
    const uint32_t dbase = (raw + 1023u) & ~1023u;
    char* dptr = dyn + (dbase - raw);

    // ---- cooperative B: emb_q fp32 -> fp16 smem (all 512 threads, once)
    {
        const int r = tid >> 1;     // 0..255
        const int h = tid & 1;
#pragma unroll
        for (int kt = 0; kt < 4; kt++) {
            const float4* src =
                (const float4*)(emb_q + (size_t)r * 256 + kt * 64 + h * 32);
            float4 v[8];
#pragma unroll
            for (int q = 0; q < 8; q++) v[q] = src[q];
#pragma unroll
            for (int cc = 0; cc < 4; cc++) {
                const int cch = h * 4 + cc;
                *(uint4*)(dptr + B_OFF + kt * 32768 + r * 128 +
                          ((cch ^ (r & 7)) << 4)) = pack8(v[2 * cc], v[2 * cc + 1]);
            }
        }
        if (tid < D_ATTN) wh_s[tid] = w_h[tid];
    }
    __syncthreads();

    if (wid >= 8) {
        // =============== prefetch group: warps 8-15 ===============
        // Warm L2 with the first 96MB of emb_iseq, ascending (k2's order).
        const int gw = cta * 8 + (wid - 8);          // 0..1183
        const float4* src = (const float4*)emb_iseq;
        float s = 0.0f;
        for (int i = gw * 32 + lane; i < PREF_F4; i += NCTA * 8 * 32) {
            const float4 v = __ldcg(&src[i]);
            s += v.x + v.y + v.z + v.w;
        }
        asm volatile("" :: "f"(s));   // sink: keep the loads alive
        return;
    }

    // =============== GEMM group: warps 0-7 (256 threads) ===============
    const int c  = tid & 7;
    const int rb = tid >> 3;
    const int wm = wid >> 2, wn = wid & 3;
    const int gid = lane >> 2, tid4 = lane & 3;
    const int lrow = lane & 7, half = (lane >> 3) & 1, hi = lane >> 4;

    uint32_t roffA[4], swzA[4], roffB[2], swzB[2];
#pragma unroll
    for (int m = 0; m < 4; m++) {
        const int r = wm * 64 + m * 16 + half * 8 + lrow;
        roffA[m] = (uint32_t)r * 128;
        swzA[m]  = (uint32_t)(r & 7);
    }
#pragma unroll
    for (int pf = 0; pf < 2; pf++) {
        const int r = wn * 32 + pf * 16 + half * 8 + lrow;
        roffB[pf] = (uint32_t)r * 128;
        swzB[pf]  = (uint32_t)(r & 7);
    }

    const int ntask = (cta < D - NCTA) ? 2 : 1;
    for (int task = 0; task < ntask; task++) {
        const int j = cta + task * NCTA;
        const float* Aj = w_f + (size_t)j * D_ATTN * D;

        // A: w_f[j] fp32 -> fp16 smem (4 rows/thread per k-tile)
#pragma unroll
        for (int kt = 0; kt < 4; kt++) {
            float4 ra[4][2];
#pragma unroll
            for (int i = 0; i < 4; i++) {
                const int r = rb + 32 * i;  // 0..127
                const float* p = Aj + (size_t)r * 256 + kt * 64 + c * 8;
                ra[i][0] = *(const float4*)p;
                ra[i][1] = *(const float4*)(p + 4);
            }
#pragma unroll
            for (int i = 0; i < 4; i++) {
                const int r = rb + 32 * i;
                *(uint4*)(dptr + kt * 16384 + r * 128 + ((c ^ (r & 7)) << 4)) =
                    pack8(ra[i][0], ra[i][1]);
            }
        }
        if (tid < D_ATTN) bias_s[tid] = b_f[j * D_ATTN + tid];
        BAR1();

        // two n-passes of 128 b-columns each
#pragma unroll
        for (int p = 0; p < 2; p++) {
            float acc[4][4][4];
#pragma unroll
            for (int m = 0; m < 4; m++)
#pragma unroll
                for (int n = 0; n < 4; n++)
#pragma unroll
                    for (int q = 0; q < 4; q++) acc[m][n][q] = 0.0f;

#pragma unroll
            for (int kt = 0; kt < 4; kt++) {
                const uint32_t aB = dbase + (uint32_t)kt * 16384;
                const uint32_t bB = dbase + B_OFF + (uint32_t)kt * 32768 +
                                    (uint32_t)p * 16384;
#pragma unroll
                for (int ks = 0; ks < 4; ks++) {
                    const uint32_t ch = (uint32_t)(ks * 2 + hi);
                    uint32_t af[4][4], bf[4][2];
#pragma unroll
                    for (int m = 0; m < 4; m++)
                        LDSM4(af[m][0], af[m][1], af[m][2], af[m][3],
                              aB + roffA[m] + ((ch ^ swzA[m]) << 4));
#pragma unroll
                    for (int pf = 0; pf < 2; pf++) {
                        uint32_t r0, r1, r2, r3;
                        LDSM4(r0, r1, r2, r3,
                              bB + roffB[pf] + ((ch ^ swzB[pf]) << 4));
                        bf[2 * pf][0] = r0; bf[2 * pf + 1][0] = r1;
                        bf[2 * pf][1] = r2; bf[2 * pf + 1][1] = r3;
                    }
#pragma unroll
                    for (int m = 0; m < 4; m++)
#pragma unroll
                        for (int n = 0; n < 4; n++)
                            mma_f16(acc[m][n], af[m], bf[n]);
                }
            }

            // epilogue: tanh + w_h reduce over a
            float biasv[4][2], whv[4][2];
#pragma unroll
            for (int m = 0; m < 4; m++)
#pragma unroll
                for (int h = 0; h < 2; h++) {
                    const int a = wm * 64 + m * 16 + h * 8 + gid;
                    biasv[m][h] = bias_s[a];
                    whv[m][h]   = wh_s[a];
                }
#pragma unroll
            for (int n = 0; n < 4; n++) {
                float p0 = 0.0f, p1 = 0.0f;
#pragma unroll
                for (int m = 0; m < 4; m++) {
                    p0 += tanh_ap(acc[m][n][0] + biasv[m][0]) * whv[m][0]
                        + tanh_ap(acc[m][n][2] + biasv[m][1]) * whv[m][1];
                    p1 += tanh_ap(acc[m][n][1] + biasv[m][0]) * whv[m][0]
                        + tanh_ap(acc[m][n][3] + biasv[m][1]) * whv[m][1];
                }
#pragma unroll
                for (int o = 4; o <= 16; o <<= 1) {
                    p0 += __shfl_xor_sync(0xffffffffu, p0, o);
                    p1 += __shfl_xor_sync(0xffffffffu, p1, o);
                }
                if (gid == 0) {
                    const int col = wn * 32 + n * 8 + tid4 * 2;
                    red[wm][col]     = p0;
                    red[wm][col + 1] = p1;
                }
            }
            BAR1();
            if (tid < 128)
                g_buf[(size_t)(p * 128 + tid) * D + j] =
                    red[0][tid] + red[1][tid];
            BAR1();
        }
    }
}

// ---------------------------------------------------------------------------
// Kernel 2: out[b,l] = sum_j emb_iseq[b,l,j] * g[b,j]
// (R5 champion config: 8 rows/warp, __ldcs streaming, grid (16, 256).)
// ---------------------------------------------------------------------------
__global__ void __launch_bounds__(256) k2_weight(
    const float* __restrict__ emb_iseq,  // [BSZ, MAX_LEN, D]
    float* __restrict__ out)             // [BSZ, MAX_LEN]
{
    const int b   = blockIdx.y;
    const int l0  = blockIdx.x * 64;
    const int tid = threadIdx.x;

    __shared__ float gs[D];
    gs[tid] = g_buf[(size_t)b * D + tid];
    __syncthreads();

    const int warp = tid >> 5;
    const int lane = tid & 31;
    const int l = l0 + warp * 8;

    const float4* base = (const float4*)(emb_iseq + ((size_t)b * MAX_LEN + l) * D);

    float4 e[8][2];
#pragma unroll
    for (int r = 0; r < 8; r++)
#pragma unroll
        for (int i = 0; i < 2; i++)
            e[r][i] = __ldcs(&base[r * 64 + i * 32 + lane]);

    const float4* gv = (const float4*)gs;
    const float4 g0 = gv[lane];
    const float4 g1 = gv[lane + 32];

    float acc[8];
#pragma unroll
    for (int r = 0; r < 8; r++) {
        acc[r] = e[r][0].x * g0.x + e[r][0].y * g0.y + e[r][0].z * g0.z +
                 e[r][0].w * g0.w + e[r][1].x * g1.x + e[r][1].y * g1.y +
                 e[r][1].z * g1.z + e[r][1].w * g1.w;
    }
#pragma unroll
    for (int r = 0; r < 8; r++)
#pragma unroll
        for (int o = 16; o; o >>= 1)
            acc[r] += __shfl_xor_sync(0xffffffffu, acc[r], o);

    if (lane == 0) {
#pragma unroll
        for (int r = 0; r < 8; r++)
            out[(size_t)b * MAX_LEN + l + r] = acc[r];
    }
}

// ---------------------------------------------------------------------------

extern "C" void kernel_launch(void* const* d_in, const int* in_sizes, int n_in,
                              void* d_out, int out_size)
{
    const float* emb_q    = (const float*)d_in[0];
    const float* emb_iseq = (const float*)d_in[1];
    const float* w_f      = (const float*)d_in[2];
    const float* b_f      = (const float*)d_in[3];
    const float* w_h      = (const float*)d_in[4];
    float* out = (float*)d_out;

    cudaFuncSetAttribute(k1_mma, cudaFuncAttributeMaxDynamicSharedMemorySize,
                         K1_SMEM);

    k1_mma<<<NCTA, 512, K1_SMEM>>>(emb_q, emb_iseq, w_f, b_f, w_h);

    dim3 g2(MAX_LEN / 64, BSZ);
    k2_weight<<<g2, 256>>>(emb_iseq, out);
}

// round 13
// speedup vs baseline: 1.3143x; 1.0292x over previous
#include <cuda_runtime.h>
#include <cuda_fp16.h>
#include <cstdint>

#define BSZ 256
#define MAX_LEN 1024
#define D 256
#define D_ATTN 128

__device__ float g_buf[BSZ * D];   // g[b][j]

// ---------------------------------------------------------------------------
__device__ __forceinline__ uint32_t smem_u32(const void* p) {
    uint32_t a;
    asm("{ .reg .u64 t; cvta.to.shared.u64 t, %1; cvt.u32.u64 %0, t; }"
        : "=r"(a) : "l"(p));
    return a;
}
__device__ __forceinline__ float tanh_ap(float x) {
    float r;
    asm("tanh.approx.f32 %0, %1;" : "=f"(r) : "f"(x));
    return r;
}
__device__ __forceinline__ void mma_f16(float c[4], const uint32_t a[4],
                                        const uint32_t b[2]) {
    asm volatile(
        "mma.sync.aligned.m16n8k16.row.col.f32.f16.f16.f32 "
        "{%0,%1,%2,%3}, {%4,%5,%6,%7}, {%8,%9}, {%0,%1,%2,%3};\n"
        : "+f"(c[0]), "+f"(c[1]), "+f"(c[2]), "+f"(c[3])
        : "r"(a[0]), "r"(a[1]), "r"(a[2]), "r"(a[3]), "r"(b[0]), "r"(b[1]));
}
#define LDSM4(r0, r1, r2, r3, addr)                                           \
    asm volatile("ldmatrix.sync.aligned.m8n8.x4.shared.b16 {%0,%1,%2,%3}, [%4];" \
                 : "=r"(r0), "=r"(r1), "=r"(r2), "=r"(r3) : "r"(addr))

__device__ __forceinline__ uint32_t pack_h2(float x, float y) {
    const __half2 h = __floats2half2_rn(x, y);
    return *(const uint32_t*)&h;
}
__device__ __forceinline__ uint4 pack8(const float4& a, const float4& b) {
    return make_uint4(pack_h2(a.x, a.y), pack_h2(a.z, a.w),
                      pack_h2(b.x, b.y), pack_h2(b.z, b.w));
}

// ---------------------------------------------------------------------------
// Kernel 1 (per b-half): grid 256 (j), 256 threads, 2 CTAs/SM.
// D[m=a(128), n=b(128)] = w_f[j] . emb_q[b0:b0+128]^T, K=256, fp16 mma.
// B: emb_q converted fp32->fp16 ONCE in the prologue into resident smem.
// A: w_f fp32 reg-staged + converted, double-buffered 2x16KB.
// ---------------------------------------------------------------------------
#define A_STG 16384
#define B_BASE 32768
#define B_TILE 16384
#define K1_SMEM (B_BASE + 4 * B_TILE + 1024)

__global__ void __launch_bounds__(256, 2) k1_mma(
    const float* __restrict__ emb_q,   // [BSZ, D]
    const float* __restrict__ w_f,     // [D, D_ATTN, D]
    const float* __restrict__ b_f,     // [D, D_ATTN]
    const float* __restrict__ w_h,     // [D_ATTN]
    const int b0)                      // 0 or 128
{
    extern __shared__ char dyn[];
    __shared__ float bias_s[D_ATTN], wh_s[D_ATTN];
    __shared__ float red[2][128];

    const int j    = blockIdx.x;
    const int tid  = threadIdx.x;
    const int lane = tid & 31;
    const int wid  = tid >> 5;
    const int wm   = wid >> 2;     // 0..1
    const int wn   = wid & 3;      // 0..3
    const int gid  = lane >> 2;
    const int tid4 = lane & 3;

    const uint32_t raw = smem_u32(dyn);
    const uint32_t dbase = (raw + 1023u) & ~1023u;
    char* dptr = dyn + (dbase - raw);

    if (tid < D_ATTN) {
        bias_s[tid] = b_f[j * D_ATTN + tid];
        wh_s[tid]   = w_h[tid];
    }

    const int c  = tid & 7;       // 16B chunk within 128B row
    const int rb = tid >> 3;      // row base (0..31)

    // ---- prologue: B = emb_q[b0:b0+128] fp32 -> fp16 resident smem (once)
#pragma unroll
    for (int kt = 0; kt < 4; kt++) {
#pragma unroll
        for (int i = 0; i < 4; i++) {
            const int r = rb + 32 * i;  // 0..127
            const float* pb = emb_q + (size_t)(b0 + r) * 256 + kt * 64 + c * 8;
            const float4 v0 = *(const float4*)pb;
            const float4 v1 = *(const float4*)(pb + 4);
            *(uint4*)(dptr + B_BASE + kt * B_TILE + r * 128 +
                      ((c ^ (r & 7)) << 4)) = pack8(v0, v1);
        }
    }

    // ---- A tile 0: load + convert + STS
    const float* Aj = w_f + (size_t)j * D_ATTN * D;
    float4 ra[4][2];
#pragma unroll
    for (int i = 0; i < 4; i++) {
        const int r = rb + 32 * i;  // 0..127
        const float* p = Aj + (size_t)r * 256 + c * 8;
        ra[i][0] = *(const float4*)p;
        ra[i][1] = *(const float4*)(p + 4);
    }
#pragma unroll
    for (int i = 0; i < 4; i++) {
        const int r = rb + 32 * i;
        *(uint4*)(dptr + r * 128 + ((c ^ (r & 7)) << 4)) =
            pack8(ra[i][0], ra[i][1]);
    }
    __syncthreads();

    // ---- ldmatrix per-thread bases
    const int lrow = lane & 7;
    const int half = (lane >> 3) & 1;
    const int hi   = lane >> 4;
    uint32_t roffA[4], swzA[4], roffB[2], swzB[2];
#pragma unroll
    for (int m = 0; m < 4; m++) {
        const int r = wm * 64 + m * 16 + half * 8 + lrow;
        roffA[m] = (uint32_t)r * 128;
        swzA[m]  = (uint32_t)(r & 7);
    }
#pragma unroll
    for (int pf = 0; pf < 2; pf++) {
        const int r = wn * 32 + pf * 16 + half * 8 + lrow;
        roffB[pf] = (uint32_t)r * 128;
        swzB[pf]  = (uint32_t)(r & 7);
    }

    float acc[4][4][4];
#pragma unroll
    for (int m = 0; m < 4; m++)
#pragma unroll
        for (int n = 0; n < 4; n++)
#pragma unroll
            for (int q = 0; q < 4; q++) acc[m][n][q] = 0.0f;

    // ---- main loop: 4 k-tiles of 64 (A double-buffered, B resident)
#pragma unroll
    for (int t = 0; t < 4; t++) {
        if (t < 3) {
#pragma unroll
            for (int i = 0; i < 4; i++) {
                const int r = rb + 32 * i;
                const float* p = Aj + (size_t)r * 256 + (t + 1) * 64 + c * 8;
                ra[i][0] = *(const float4*)p;
                ra[i][1] = *(const float4*)(p + 4);
            }
        }

        const uint32_t aB = dbase + (uint32_t)(t & 1) * A_STG;
        const uint32_t bB = dbase + B_BASE + (uint32_t)t * B_TILE;
#pragma unroll
        for (int ks = 0; ks < 4; ks++) {
            const uint32_t ch = (uint32_t)(ks * 2 + hi);
            uint32_t af[4][4], bf[4][2];
#pragma unroll
            for (int m = 0; m < 4; m++)
                LDSM4(af[m][0], af[m][1], af[m][2], af[m][3],
                      aB + roffA[m] + ((ch ^ swzA[m]) << 4));
#pragma unroll
            for (int pf = 0; pf < 2; pf++) {
                uint32_t r0, r1, r2, r3;
                LDSM4(r0, r1, r2, r3, bB + roffB[pf] + ((ch ^ swzB[pf]) << 4));
                bf[2 * pf][0] = r0; bf[2 * pf + 1][0] = r1;
                bf[2 * pf][1] = r2; bf[2 * pf + 1][1] = r3;
            }
#pragma unroll
            for (int m = 0; m < 4; m++)
#pragma unroll
                for (int n = 0; n < 4; n++) mma_f16(acc[m][n], af[m], bf[n]);
        }

        if (t < 3) {
            __syncthreads();
            char* dp = dptr + ((t + 1) & 1) * A_STG;
#pragma unroll
            for (int i = 0; i < 4; i++) {
                const int r = rb + 32 * i;
                *(uint4*)(dp + r * 128 + ((c ^ (r & 7)) << 4)) =
                    pack8(ra[i][0], ra[i][1]);
            }
            __syncthreads();
        }
    }

    // ---- epilogue: g[b][j] = sum_a tanh(D[a,b] + bias[a]) * wh[a]
    float biasv[4][2], whv[4][2];
#pragma unroll
    for (int m = 0; m < 4; m++)
#pragma unroll
        for (int h = 0; h < 2; h++) {
            const int a = wm * 64 + m * 16 + h * 8 + gid;
            biasv[m][h] = bias_s[a];
            whv[m][h]   = wh_s[a];
        }

#pragma unroll
    for (int n = 0; n < 4; n++) {
        float p0 = 0.0f, p1 = 0.0f;
#pragma unroll
        for (int m = 0; m < 4; m++) {
            p0 += tanh_ap(acc[m][n][0] + biasv[m][0]) * whv[m][0]
                + tanh_ap(acc[m][n][2] + biasv[m][1]) * whv[m][1];
            p1 += tanh_ap(acc[m][n][1] + biasv[m][0]) * whv[m][0]
                + tanh_ap(acc[m][n][3] + biasv[m][1]) * whv[m][1];
        }
#pragma unroll
        for (int o = 4; o <= 16; o <<= 1) {
            p0 += __shfl_xor_sync(0xffffffffu, p0, o);
            p1 += __shfl_xor_sync(0xffffffffu, p1, o);
        }
        if (gid == 0) {
            const int col = wn * 32 + n * 8 + tid4 * 2;
            red[wm][col]     = p0;
            red[wm][col + 1] = p1;
        }
    }
    __syncthreads();
    if (tid < 128)
        g_buf[(size_t)(b0 + tid) * D + j] = red[0][tid] + red[1][tid];
}

// ---------------------------------------------------------------------------
// Kernel 2 (per b-half): out[b,l] = sum_j emb_iseq[b,l,j] * g[b,j]
// Champion config: 8 rows/warp, __ldcs, grid (16, 128) per half.
// ---------------------------------------------------------------------------
__global__ void __launch_bounds__(256) k2_weight(
    const float* __restrict__ emb_iseq,  // [BSZ, MAX_LEN, D]
    float* __restrict__ out,             // [BSZ, MAX_LEN]
    const int b0)
{
    const int b   = b0 + blockIdx.y;
    const int l0  = blockIdx.x * 64;
    const int tid = threadIdx.x;

    __shared__ float gs[D];
    gs[tid] = g_buf[(size_t)b * D + tid];
    __syncthreads();

    const int warp = tid >> 5;
    const int lane = tid & 31;
    const int l = l0 + warp * 8;

    const float4* base = (const float4*)(emb_iseq + ((size_t)b * MAX_LEN + l) * D);

    float4 e[8][2];
#pragma unroll
    for (int r = 0; r < 8; r++)
#pragma unroll
        for (int i = 0; i < 2; i++)
            e[r][i] = __ldcs(&base[r * 64 + i * 32 + lane]);

    const float4* gv = (const float4*)gs;
    const float4 g0 = gv[lane];
    const float4 g1 = gv[lane + 32];

    float acc[8];
#pragma unroll
    for (int r = 0; r < 8; r++) {
        acc[r] = e[r][0].x * g0.x + e[r][0].y * g0.y + e[r][0].z * g0.z +
                 e[r][0].w * g0.w + e[r][1].x * g1.x + e[r][1].y * g1.y +
                 e[r][1].z * g1.z + e[r][1].w * g1.w;
    }
#pragma unroll
    for (int r = 0; r < 8; r++)
#pragma unroll
        for (int o = 16; o; o >>= 1)
            acc[r] += __shfl_xor_sync(0xffffffffu, acc[r], o);

    if (lane == 0) {
#pragma unroll
        for (int r = 0; r < 8; r++)
            out[(size_t)b * MAX_LEN + l + r] = acc[r];
    }
}

// ---------------------------------------------------------------------------
// Launcher.
// Preferred: stream-fork pipeline  k1a -> { k2a || s2: k1b } -> k2b
// Fallback (if stream/event creation fails on this system): serial schedule.
// Resources are created on the FIRST call (the uncaptured correctness run);
// any failure selects the serial path permanently and clears the error.
// ---------------------------------------------------------------------------

extern "C" void kernel_launch(void* const* d_in, const int* in_sizes, int n_in,
                              void* d_out, int out_size)
{
    const float* emb_q    = (const float*)d_in[0];
    const float* emb_iseq = (const float*)d_in[1];
    const float* w_f      = (const float*)d_in[2];
    const float* b_f      = (const float*)d_in[3];
    const float* w_h      = (const float*)d_in[4];
    float* out = (float*)d_out;

    static int fork_ok = -1;
    static cudaStream_t s2 = nullptr;
    static cudaEvent_t evA = nullptr, evB = nullptr;

    if (fork_ok < 0) {
        cudaFuncSetAttribute(k1_mma,
                             cudaFuncAttributeMaxDynamicSharedMemorySize,
                             K1_SMEM);
        fork_ok = 1;
        if (cudaStreamCreateWithFlags(&s2, cudaStreamNonBlocking) != cudaSuccess)
            fork_ok = 0;
        if (fork_ok &&
            cudaEventCreateWithFlags(&evA, cudaEventDisableTiming) != cudaSuccess)
            fork_ok = 0;
        if (fork_ok &&
            cudaEventCreateWithFlags(&evB, cudaEventDisableTiming) != cudaSuccess)
            fork_ok = 0;
        cudaGetLastError();   // clear any creation error; fallback is serial
    }

    const dim3 g2(MAX_LEN / 64, BSZ / 2);

    if (fork_ok) {
        // k1a: g for b in [0,128)
        k1_mma<<<D, 256, K1_SMEM>>>(emb_q, w_f, b_f, w_h, 0);
        cudaEventRecord(evA, 0);

        // fork: k1b on s2, parallel with k2a on the main stream
        cudaStreamWaitEvent(s2, evA, 0);
        k1_mma<<<D, 256, K1_SMEM, s2>>>(emb_q, w_f, b_f, w_h, 128);
        cudaEventRecord(evB, s2);

        // k2a: consumes b in [0,128)
        k2_weight<<<g2, 256>>>(emb_iseq, out, 0);

        // join, then k2b
        cudaStreamWaitEvent(0, evB, 0);
        k2_weight<<<g2, 256>>>(emb_iseq, out, 128);
    } else {
        // serial fallback (same kernels, default stream)
        k1_mma<<<D, 256, K1_SMEM>>>(emb_q, w_f, b_f, w_h, 0);
        k1_mma<<<D, 256, K1_SMEM>>>(emb_q, w_f, b_f, w_h, 128);
        k2_weight<<<g2, 256>>>(emb_iseq, out, 0);
        k2_weight<<<g2, 256>>>(emb_iseq, out, 128);
    }
}